// round 2
// baseline (speedup 1.0000x reference)
#include <cuda_runtime.h>
#include <cstdint>

// Irreps: 256x0e + 128x1o + 64x2e + 32x3o
// DIM = 1184, WNUM = 480
// Per block: out[n,w,i] = (1/m) * sum_u x[n,u,i] * weight[n,u] * W[u,w]

#define DIM_ 1184
#define WNUM_ 480

template<int D, int M, int BN, int BW, int BK, int TN, int TW>
__global__ __launch_bounds__(256)
void tp_linear_kernel(const float* __restrict__ x,
                      const float* __restrict__ wt,
                      const float* __restrict__ Wm,
                      float* __restrict__ out,
                      int nrows, int xo, int wo)
{
    constexpr int AF  = TN * D;        // A-frag floats per thread per k
    constexpr int THW = BW / TW;       // threads along w  (=16)
    constexpr int THN = BN / TN;       // threads along n  (=16)
    static_assert(THW * THN == 256, "thread grid");
    static_assert((BK * D) % 4 == 0, "A row chunk vec4");
    static_assert(AF % 4 == 0, "A frag vec4");
    static_assert((TN * D * 4) % 16 == 0, "A frag align");

    __shared__ float As[BK][BN * D];   // As[k][r*D + i] = x*wt*(1/m)
    __shared__ float Bs[BK][BW];       // Bs[k][w] = W[u0+k][w0+w]

    const int tid = threadIdx.x;
    const int twi = tid % THW;
    const int tni = tid / THW;
    const int n0  = blockIdx.x * BN;
    const int w0  = blockIdx.y * BW;
    const int tn0 = tni * TN;
    const int bw  = twi * TW;
    const float inv_m = 1.0f / (float)M;

    // packed f32x2 accumulators: acc[e][j2] holds (w=bw+2*j2, w=bw+2*j2+1)
    unsigned long long acc[AF][TW / 2];
#pragma unroll
    for (int e = 0; e < AF; ++e)
#pragma unroll
        for (int j2 = 0; j2 < TW / 2; ++j2) acc[e][j2] = 0ull;

    for (int u0 = 0; u0 < M; u0 += BK) {
        __syncthreads();

        // ---- load B tile: W[u0+k][w0 + 0..BW) ----
        constexpr int BV = BW / 4;
        for (int idx = tid; idx < BK * BV; idx += 256) {
            int k  = idx / BV;
            int cv = (idx % BV) * 4;
            float4 v = *reinterpret_cast<const float4*>(
                Wm + (size_t)(u0 + k) * M + w0 + cv);
            *reinterpret_cast<float4*>(&Bs[k][cv]) = v;
        }

        // ---- load A tile: contiguous x chunk, scaled by wt * 1/m ----
        constexpr int CV = (BK * D) / 4;   // vec4 per row
        for (int idx = tid; idx < BN * CV; idx += 256) {
            int r  = idx / CV;
            int cv = (idx % CV) * 4;
            int gn = n0 + r;
            if (gn < nrows) {
                float4 v = *reinterpret_cast<const float4*>(
                    x + (size_t)gn * DIM_ + xo + u0 * D + cv);
                const float* vf = reinterpret_cast<const float*>(&v);
#pragma unroll
                for (int j = 0; j < 4; ++j) {
                    int c = cv + j;
                    int k = c / D;
                    int i = c - k * D;
                    float wv = __ldg(wt + (size_t)gn * WNUM_ + wo + u0 + k) * inv_m;
                    As[k][r * D + i] = vf[j] * wv;
                }
            } else {
#pragma unroll
                for (int j = 0; j < 4; ++j) {
                    int c = cv + j;
                    int k = c / D;
                    int i = c - k * D;
                    As[k][r * D + i] = 0.0f;
                }
            }
        }
        __syncthreads();

        // ---- FMA loop ----
#pragma unroll
        for (int k = 0; k < BK; ++k) {
            float4 af[AF / 4];
#pragma unroll
            for (int q = 0; q < AF / 4; ++q)
                af[q] = *reinterpret_cast<const float4*>(&As[k][tn0 * D + q * 4]);

            unsigned long long bf[TW / 2];
            const unsigned long long* brow =
                reinterpret_cast<const unsigned long long*>(&Bs[k][0]);
#pragma unroll
            for (int j2 = 0; j2 < TW / 2; ++j2) bf[j2] = brow[bw / 2 + j2];

            const float* afl = reinterpret_cast<const float*>(af);
#pragma unroll
            for (int e = 0; e < AF; ++e) {
                unsigned long long a2;
                asm("mov.b64 %0, {%1, %1};"
                    : "=l"(a2) : "r"(__float_as_uint(afl[e])));
#pragma unroll
                for (int j2 = 0; j2 < TW / 2; ++j2) {
                    asm("fma.rn.f32x2 %0, %1, %2, %0;"
                        : "+l"(acc[e][j2]) : "l"(a2), "l"(bf[j2]));
                }
            }
        }
    }

    // ---- epilogue ----
    // global w for accumulator (e, j2) pair: w0 + bw + 2*j2 (+1)
#pragma unroll
    for (int a = 0; a < TN; ++a) {
        int gn = n0 + tn0 + a;
        if (gn >= nrows) continue;
        float* orow = out + (size_t)gn * DIM_ + xo + (size_t)w0 * D;
#pragma unroll
        for (int j2 = 0; j2 < TW / 2; ++j2) {
#pragma unroll
            for (int i = 0; i < D; ++i) {
                unsigned long long v = acc[a * D + i][j2];
                float lo = __uint_as_float((unsigned)(v & 0xffffffffull));
                float hi = __uint_as_float((unsigned)(v >> 32));
                if (D == 1) {
                    float2 p = make_float2(lo, hi);
                    *reinterpret_cast<float2*>(&orow[bw + 2 * j2]) = p;
                } else {
                    orow[(bw + 2 * j2) * D + i]     = lo;
                    orow[(bw + 2 * j2 + 1) * D + i] = hi;
                }
            }
        }
    }
}

extern "C" void kernel_launch(void* const* d_in, const int* in_sizes, int n_in,
                              void* d_out, int out_size)
{
    const float* x  = (const float*)d_in[0];
    const float* wt = (const float*)d_in[1];
    const float* W0 = (const float*)d_in[2];
    const float* W1 = (const float*)d_in[3];
    const float* W2 = (const float*)d_in[4];
    const float* W3 = (const float*)d_in[5];
    float* out = (float*)d_out;

    const int nrows = in_sizes[0] / DIM_;
    dim3 blk(256);

    // block 0: m=256, d=1, xo=0,   wo=0
    tp_linear_kernel<1, 256, 128, 128, 16, 8, 8>
        <<<dim3((nrows + 127) / 128, 2), blk>>>(x, wt, W0, out, nrows, 0, 0);
    // block 1: m=128, d=3, xo=256, wo=256
    tp_linear_kernel<3, 128, 64, 128, 16, 4, 8>
        <<<dim3((nrows + 63) / 64, 1), blk>>>(x, wt, W1, out, nrows, 256, 256);
    // block 2: m=64, d=5, xo=640, wo=384
    tp_linear_kernel<5, 64, 64, 64, 16, 4, 4>
        <<<dim3((nrows + 63) / 64, 1), blk>>>(x, wt, W2, out, nrows, 640, 384);
    // block 3: m=32, d=7, xo=960, wo=448
    tp_linear_kernel<7, 32, 64, 32, 16, 4, 2>
        <<<dim3((nrows + 63) / 64, 1), blk>>>(x, wt, W3, out, nrows, 960, 448);
}

// round 3
// speedup vs baseline: 1.8723x; 1.8723x over previous
#include <cuda_runtime.h>
#include <cstdint>

// out[n,w,i] = (1/m) * sum_u x[n,u,i] * weight[n,u] * W[u,w]
// Irreps: 256x0e + 128x1o + 64x2e + 32x3o ; DIM=1184, WNUM=480

#define DIM_ 1184
#define WNUM_ 480
typedef unsigned long long ull;

__device__ __forceinline__ void cp_async16(uint32_t dst, const void* src) {
    asm volatile("cp.async.cg.shared.global [%0], [%1], 16;" :: "r"(dst), "l"(src));
}
__device__ __forceinline__ void cp_commit() { asm volatile("cp.async.commit_group;"); }
__device__ __forceinline__ void cp_wait0()  { asm volatile("cp.async.wait_group 0;" ::: "memory"); }

template<int D, int M, int BN, int BW, int BK, int TN, int TW>
__global__ __launch_bounds__(256)
void tp2_kernel(const float* __restrict__ x, const float* __restrict__ wt,
                const float* __restrict__ Wm, float* __restrict__ out,
                int nrows, int xo, int wo)
{
    constexpr int THW = BW / TW;
    constexpr int THN = BN / TN;
    static_assert(THW * THN == 256, "thread grid");
    constexpr int RT  = 256 / BN;      // fill threads per row
    constexpr int KPT = BK / RT;       // wt floats per fill thread
    constexpr int CPT = KPT * D;       // x floats per fill thread
    constexpr int AF  = TN * D;        // A-frag floats
    static_assert((BN * D) % 4 == 0, "rowlen");
    constexpr int ROWLEN = BN * D + 4; // padded (mult of 4, bank stagger 4k)
    constexpr int TILES = M / BK;
    constexpr int NB4 = BK * BW / 4;   // float4s in B tile
    static_assert(CPT % 2 == 0, "x vec2");
    static_assert(KPT % 2 == 0, "wt vec2");

    __shared__ float As[2][BK][ROWLEN];
    __shared__ float Bs[2][BK][BW];

    const int tid = threadIdx.x;
    const int twi = tid % THW;
    const int tni = tid / THW;
    const int n0  = blockIdx.x * BN;
    const int rf  = tid / RT;
    const int q   = tid % RT;
    const bool rvalid = (n0 + rf) < nrows;
    const float inv_m = 1.0f / (float)M;

    const float* xrow = x  + (size_t)(n0 + rf) * DIM_  + xo + q * CPT;
    const float* wrow = wt + (size_t)(n0 + rf) * WNUM_ + wo + q * KPT;
    const uint32_t bs0 = (uint32_t)__cvta_generic_to_shared(&Bs[0][0][0]);

    ull acc[AF][TW / 2];
#pragma unroll
    for (int e = 0; e < AF; ++e)
#pragma unroll
        for (int j2 = 0; j2 < TW / 2; ++j2) acc[e][j2] = 0ull;

    alignas(16) float xr[CPT];
    alignas(16) float wr[KPT];

    auto ld_regs = [&](int u0) {
        if (rvalid) {
            const float* xp = xrow + (size_t)u0 * D;
            if constexpr (CPT % 4 == 0) {
#pragma unroll
                for (int v = 0; v < CPT / 4; ++v)
                    reinterpret_cast<float4*>(xr)[v] =
                        reinterpret_cast<const float4*>(xp)[v];
            } else {
#pragma unroll
                for (int v = 0; v < CPT / 2; ++v)
                    reinterpret_cast<float2*>(xr)[v] =
                        reinterpret_cast<const float2*>(xp)[v];
            }
            const float* wp = wrow + u0;
            if constexpr (KPT % 4 == 0) {
#pragma unroll
                for (int v = 0; v < KPT / 4; ++v)
                    reinterpret_cast<float4*>(wr)[v] =
                        reinterpret_cast<const float4*>(wp)[v];
            } else {
#pragma unroll
                for (int v = 0; v < KPT / 2; ++v)
                    reinterpret_cast<float2*>(wr)[v] =
                        reinterpret_cast<const float2*>(wp)[v];
            }
        } else {
#pragma unroll
            for (int j = 0; j < CPT; ++j) xr[j] = 0.0f;
#pragma unroll
            for (int j = 0; j < KPT; ++j) wr[j] = 0.0f;
        }
    };

    auto ld_bs = [&](int u0, int buf) {
        const float4* src = reinterpret_cast<const float4*>(Wm + (size_t)u0 * BW);
        uint32_t dst = bs0 + (uint32_t)buf * (BK * BW * 4);
#pragma unroll
        for (int v = 0; v < (NB4 + 255) / 256; ++v) {
            int idx = tid + v * 256;
            if ((NB4 % 256 == 0) || idx < NB4)
                cp_async16(dst + idx * 16, src + idx);
        }
    };

    auto st_as = [&](int buf) {
#pragma unroll
        for (int j = 0; j < CPT; ++j) {
            int kk = q * KPT + j / D;
            int ii = j % D;
            As[buf][kk][rf * D + ii] = xr[j] * (wr[j / D] * inv_m);
        }
    };

    auto compute = [&](int buf) {
#pragma unroll
        for (int k = 0; k < BK; ++k) {
            alignas(16) float af[AF];
            const float* ap = &As[buf][k][tni * TN * D];
            if constexpr (AF % 4 == 0) {
#pragma unroll
                for (int v = 0; v < AF / 4; ++v)
                    reinterpret_cast<float4*>(af)[v] =
                        reinterpret_cast<const float4*>(ap)[v];
            } else if constexpr (AF % 2 == 0) {
#pragma unroll
                for (int v = 0; v < AF / 2; ++v)
                    reinterpret_cast<float2*>(af)[v] =
                        reinterpret_cast<const float2*>(ap)[v];
            } else {
#pragma unroll
                for (int v = 0; v < AF; ++v) af[v] = ap[v];
            }
            ull bf[TW / 2];
            const ull* bp = reinterpret_cast<const ull*>(&Bs[buf][k][0]);
#pragma unroll
            for (int j2 = 0; j2 < TW / 2; ++j2) bf[j2] = bp[twi + j2 * THW];
#pragma unroll
            for (int e = 0; e < AF; ++e) {
                ull a2;
                asm("mov.b64 %0, {%1, %1};" : "=l"(a2) : "r"(__float_as_uint(af[e])));
#pragma unroll
                for (int j2 = 0; j2 < TW / 2; ++j2)
                    asm("fma.rn.f32x2 %0, %1, %2, %0;"
                        : "+l"(acc[e][j2]) : "l"(a2), "l"(bf[j2]));
            }
        }
    };

    // prologue: tile 0
    ld_regs(0);
    ld_bs(0, 0);
    cp_commit();
    st_as(0);
    cp_wait0();
    __syncthreads();

#pragma unroll 1
    for (int t = 0; t < TILES; ++t) {
        const int cur = t & 1;
        if (t + 1 < TILES) {
            ld_regs((t + 1) * BK);
            ld_bs((t + 1) * BK, cur ^ 1);
            cp_commit();
        }
        compute(cur);
        if (t + 1 < TILES) {
            st_as(cur ^ 1);
            cp_wait0();
        }
        __syncthreads();
    }

    // epilogue: w = twi*2 + j2*2*THW (interleaved pairs, conflict-free)
#pragma unroll
    for (int a = 0; a < TN; ++a) {
        int gn = n0 + tni * TN + a;
        if (gn >= nrows) continue;
        float* orow = out + (size_t)gn * DIM_ + xo;
#pragma unroll
        for (int j2 = 0; j2 < TW / 2; ++j2) {
            int wlo = twi * 2 + j2 * 2 * THW;
#pragma unroll
            for (int i = 0; i < D; ++i) {
                ull v = acc[a * D + i][j2];
                float lo = __uint_as_float((uint32_t)(v & 0xffffffffull));
                float hi = __uint_as_float((uint32_t)(v >> 32));
                if constexpr (D == 1) {
                    *reinterpret_cast<float2*>(orow + wlo) = make_float2(lo, hi);
                } else {
                    orow[(size_t)wlo * D + i]       = lo;
                    orow[(size_t)(wlo + 1) * D + i] = hi;
                }
            }
        }
    }
}

extern "C" void kernel_launch(void* const* d_in, const int* in_sizes, int n_in,
                              void* d_out, int out_size)
{
    const float* x  = (const float*)d_in[0];
    const float* wtp = (const float*)d_in[1];
    const float* W0 = (const float*)d_in[2];
    const float* W1 = (const float*)d_in[3];
    const float* W2 = (const float*)d_in[4];
    const float* W3 = (const float*)d_in[5];
    float* out = (float*)d_out;

    const int nrows = in_sizes[0] / DIM_;

    // block 0: m=256, d=1  (THN=8,  THW=32)
    tp2_kernel<1, 256, 64, 256, 16, 8, 8>
        <<<(nrows + 63) / 64, 256>>>(x, wtp, W0, out, nrows, 0, 0);
    // block 1: m=128, d=3  (THN=16, THW=16)
    tp2_kernel<3, 128, 32, 128, 16, 2, 8>
        <<<(nrows + 31) / 32, 256>>>(x, wtp, W1, out, nrows, 256, 256);
    // block 2: m=64, d=5   (THN=32, THW=8)
    tp2_kernel<5, 64, 32, 64, 16, 1, 8>
        <<<(nrows + 31) / 32, 256>>>(x, wtp, W2, out, nrows, 640, 384);
    // block 3: m=32, d=7   (THN=32, THW=8)
    tp2_kernel<7, 32, 32, 32, 16, 1, 4>
        <<<(nrows + 31) / 32, 256>>>(x, wtp, W3, out, nrows, 960, 448);
}